// round 8
// baseline (speedup 1.0000x reference)
#include <cuda_runtime.h>
#include <math.h>

#define BN 8192
#define FN 8192
#define DN 1024
#define H1N 256
#define H2N 64
#define NZC 102
#define CAP 224
#define MARGIN 0.22f

// ---------------- scratch (device globals; no allocations allowed) ----------
__device__ float g_a1[BN * H1N];
__device__ float g_a2[BN * H2N];
__device__ double g_ps[64 * 256], g_pq[64 * 256];     // layer-1 stats partials
__device__ double g_ps2[512 * 64], g_pq2[512 * 64];   // layer-2 stats partials
__device__ int   g_ind[BN];

// ---------------- threefry-2x32, key = (0, 42) ------------------------------
__device__ __forceinline__ unsigned int jax_bits(unsigned int j) {
    const unsigned int k0 = 0u, k1 = 42u;
    const unsigned int k2 = 0x1BD11BDAu ^ k0 ^ k1;
    unsigned int x0 = 0u + k0, x1 = j + k1;
#define TF_R(r) { x0 += x1; x1 = (x1 << (r)) | (x1 >> (32 - (r))); x1 ^= x0; }
    TF_R(13) TF_R(15) TF_R(26) TF_R(6)
    x0 += k1; x1 += k2 + 1u;
    TF_R(17) TF_R(29) TF_R(16) TF_R(24)
    x0 += k2; x1 += k0 + 2u;
    TF_R(13) TF_R(15) TF_R(26) TF_R(6)
    x0 += k0; x1 += k1 + 3u;
    TF_R(17) TF_R(29) TF_R(16) TF_R(24)
    x0 += k1; x1 += k2 + 4u;
    TF_R(13) TF_R(15) TF_R(26) TF_R(6)
    x0 += k2; x1 += k0 + 5u;
#undef TF_R
    return x0 ^ x1;   // partitionable 32-bit: bits1 ^ bits2
}

__device__ __forceinline__ float gumbel_ref(unsigned int b) {
    float u = __uint_as_float((b >> 9) | 0x3F800000u) - 1.0f;   // [0,1)
    float U = __fmul_rn(0.001f, u);
    float t = __fadd_rn(U, 0.001f);
    float l1 = logf(t);
    float a  = __fadd_rn(-l1, 0.001f);
    return -logf(a);                      // [-1.93285, -1.82711]
}

__device__ __forceinline__ unsigned int encf(float f) {
    unsigned int u = __float_as_uint(f);
    return (u & 0x80000000u) ? ~u : (u | 0x80000000u);
}
__device__ __forceinline__ float decf(unsigned int e) {
    unsigned int u = (e & 0x80000000u) ? (e ^ 0x80000000u) : ~e;
    return __uint_as_float(u);
}

// ---------------- bf16 helpers ----------------------------------------------
__device__ __forceinline__ unsigned pkbf(float lo, float hi) {
    unsigned r;
    asm("cvt.rn.bf16x2.f32 %0, %1, %2;" : "=r"(r) : "f"(hi), "f"(lo));
    return r;   // {hi:hi, lo:lo}
}
__device__ __forceinline__ void mma_bf16(float* c, const unsigned* a,
                                         unsigned b0, unsigned b1) {
    asm("mma.sync.aligned.m16n8k16.row.col.f32.bf16.bf16.f32 "
        "{%0,%1,%2,%3},{%4,%5,%6,%7},{%8,%9},{%0,%1,%2,%3};"
        : "+f"(c[0]), "+f"(c[1]), "+f"(c[2]), "+f"(c[3])
        : "r"(a[0]), "r"(a[1]), "r"(a[2]), "r"(a[3]), "r"(b0), "r"(b1));
}

// ---------------- K1: a1 = concat(x,y) @ W1 + b1 ----------------------------
__global__ __launch_bounds__(256) void k1_gemm1(const float* __restrict__ x,
                                                const float* __restrict__ y,
                                                const float* __restrict__ W1,
                                                const float* __restrict__ b1) {
    __shared__ float zs[8][NZC];
    const int rb = blockIdx.x * 8;
    const int tid = threadIdx.x;
    for (int i = tid; i < 8 * NZC; i += 256) {
        int r = i / NZC, c = i % NZC;
        zs[r][c] = (c < 100) ? x[(rb + r) * 100 + c] : y[(rb + r) * 2 + (c - 100)];
    }
    __syncthreads();
    const int col = tid;
    float acc[8];
#pragma unroll
    for (int r = 0; r < 8; r++) acc[r] = 0.0f;
    for (int k = 0; k < NZC; k++) {
        float w = W1[k * 256 + col];
#pragma unroll
        for (int r = 0; r < 8; r++) acc[r] = fmaf(zs[r][k], w, acc[r]);
    }
    const float bb = b1[col];
#pragma unroll
    for (int r = 0; r < 8; r++) g_a1[(rb + r) * 256 + col] = acc[r] + bb;
}

// ---------------- kstats1: layer-1 per-column double partials ---------------
__global__ __launch_bounds__(256) void kstats1() {
    const int tid = threadIdx.x, b = blockIdx.x;   // 64 blocks
    double s0 = 0.0, s1 = 0.0, q0 = 0.0, q1 = 0.0;
    const int rb = b * 128;
    for (int s = 0; s < 128; s += 2) {
        float v0 = g_a1[(rb + s) * 256 + tid];
        float v1 = g_a1[(rb + s + 1) * 256 + tid];
        s0 += (double)v0; q0 = fma((double)v0, (double)v0, q0);
        s1 += (double)v1; q1 = fma((double)v1, (double)v1, q1);
    }
    g_ps[b * 256 + tid] = s0 + s1;
    g_pq[b * 256 + tid] = q0 + q1;
}

// ---------------- K3 fused: stats2(L1) + relu(BN(a1)) @ W2 + b2 + L2 partials
__global__ __launch_bounds__(256) void k3_fused(const float* __restrict__ W2,
                                                const float* __restrict__ b2,
                                                const float* __restrict__ g1v,
                                                const float* __restrict__ be1) {
    extern __shared__ float sm3[];
    float* W2s = sm3;                          // 16384 floats (64KB)
    float* h1s = sm3 + 16384;                  // 16*256
    double* sst = (double*)(sm3 + 16384 + 4096);   // 256 doubles
    double* qst = sst + 256;
    __shared__ float sc1s[256], sh1s[256];
    const int tid = threadIdx.x;
    const int rb = blockIdx.x * 16;

    // layer-1 scale/shift from partials (fixed order, redundant per block)
    {
        double sa = 0.0, sb = 0.0, qa = 0.0, qb = 0.0;
        for (int b = 0; b < 64; b += 2) {
            sa += g_ps[b * 256 + tid];       qa += g_pq[b * 256 + tid];
            sb += g_ps[(b + 1) * 256 + tid]; qb += g_pq[(b + 1) * 256 + tid];
        }
        double s = sa + sb, q = qa + qb;
        double mean = s / (double)BN;
        double var  = q / (double)BN - mean * mean;
        float rstd = (float)(1.0 / sqrt(var + 1e-5));
        float scale = g1v[tid] * rstd;
        sc1s[tid] = scale;
        sh1s[tid] = be1[tid] - (float)mean * scale;
    }
    // stage W2 into smem
    for (int i = tid * 4; i < 16384; i += 1024)
        *reinterpret_cast<float4*>(&W2s[i]) = *reinterpret_cast<const float4*>(&W2[i]);
    __syncthreads();
#pragma unroll 4
    for (int r = 0; r < 16; r++) {
        float v = g_a1[(rb + r) * 256 + tid] * sc1s[tid] + sh1s[tid];
        h1s[r * 256 + tid] = fmaxf(v, 0.0f);
    }
    __syncthreads();

    const int c  = tid & 63;
    const int rq = tid >> 6;
    float acc[4] = {0.f, 0.f, 0.f, 0.f};
    for (int k = 0; k < 256; k += 4) {
        float w0 = W2s[(k + 0) * 64 + c];
        float w1 = W2s[(k + 1) * 64 + c];
        float w2v = W2s[(k + 2) * 64 + c];
        float w3v = W2s[(k + 3) * 64 + c];
#pragma unroll
        for (int i = 0; i < 4; i++) {
            const float4 h = *reinterpret_cast<const float4*>(&h1s[(rq * 4 + i) * 256 + k]);
            acc[i] = fmaf(h.x, w0, acc[i]);
            acc[i] = fmaf(h.y, w1, acc[i]);
            acc[i] = fmaf(h.z, w2v, acc[i]);
            acc[i] = fmaf(h.w, w3v, acc[i]);
        }
    }
    const float bc = b2[c];
    float o[4];
#pragma unroll
    for (int i = 0; i < 4; i++) {
        o[i] = acc[i] + bc;
        g_a2[(rb + rq * 4 + i) * 64 + c] = o[i];
    }
    // per-block layer-2 partial stats (fixed order)
    double s = (((double)o[0] + (double)o[1]) + (double)o[2]) + (double)o[3];
    double q = 0.0;
#pragma unroll
    for (int i = 0; i < 4; i++) q = fma((double)o[i], (double)o[i], q);
    sst[rq * 64 + c] = s; qst[rq * 64 + c] = q;
    __syncthreads();
    if (rq == 0) {
        double S = ((sst[c] + sst[64 + c]) + sst[128 + c]) + sst[192 + c];
        double Q = ((qst[c] + qst[64 + c]) + qst[128 + c]) + qst[192 + c];
        g_ps2[blockIdx.x * 64 + c] = S;
        g_pq2[blockIdx.x * 64 + c] = Q;
    }
}

// ---------------- K5: bf16 MMA logits + bounded-gumbel candidate argmax -----
// 128 blocks x 64 rows. Single barrier per 64-feature tile (double-buffered W,
// pre-packed bf16x2 k-pairs, bank-conflict-free). Running row max: register
// maxima + rare guarded smem atomicMax; thresholds read stale (safe superset).
// Exact fp32+threefry refine decides winners.
__global__ __launch_bounds__(256) void k5_mma(const float* __restrict__ W3,
                                              const float* __restrict__ b3,
                                              const float* __restrict__ g2v,
                                              const float* __restrict__ be2) {
    extern __shared__ char sm_[];
    float*    h2f  = (float*)sm_;                       // [64][68]
    unsigned* wsb  = (unsigned*)(h2f + 64 * 68);        // 2 x [32 kp][72]
    int*      cand = (int*)(wsb + 2 * 32 * 72);         // [64][CAP]
    unsigned* rmx  = (unsigned*)(cand + 64 * CAP);      // [64]
    int*      scnt = (int*)(rmx + 64);                  // [64]
    double*   sred = (double*)cand;                     // prologue alias
    double*   qred = sred + 256;
    __shared__ float sc2s[64], sh2s[64];

    const int tid = threadIdx.x, lane = tid & 31, wid = tid >> 5;
    const int g = lane >> 2, c4 = lane & 3;
    const int rb = blockIdx.x * 64;

    // ---- layer-2 scale/shift from k3 partials (fixed order) ----
    {
        const int c = tid & 63, part = tid >> 6;
        double sa = 0.0, sb = 0.0, qa = 0.0, qb = 0.0;
        const int b0p = part * 128;
        for (int b = 0; b < 128; b += 2) {
            sa += g_ps2[(b0p + b) * 64 + c];     qa += g_pq2[(b0p + b) * 64 + c];
            sb += g_ps2[(b0p + b + 1) * 64 + c]; qb += g_pq2[(b0p + b + 1) * 64 + c];
        }
        sred[part * 64 + c] = sa + sb;
        qred[part * 64 + c] = qa + qb;
    }
    __syncthreads();
    if (tid < 64) {
        const int c = tid;
        double S = ((sred[c] + sred[64 + c]) + sred[128 + c]) + sred[192 + c];
        double Q = ((qred[c] + qred[64 + c]) + qred[128 + c]) + qred[192 + c];
        double mean = S / (double)BN;
        double var  = Q / (double)BN - mean * mean;
        float rstd = (float)(1.0 / sqrt(var + 1e-5));
        float scale = g2v[c] * rstd;
        sc2s[c] = scale;
        sh2s[c] = be2[c] - (float)mean * scale;
    }
    __syncthreads();

    // ---- h2 staging ----
    for (int i = tid; i < 64 * 64; i += 256) {
        int r = i >> 6, k = i & 63;
        float v = g_a2[(rb + r) * 64 + k] * sc2s[k] + sh2s[k];
        h2f[r * 68 + k] = fmaxf(v, 0.0f);
    }
    if (tid < 64) { rmx[tid] = encf(-1e30f); scnt[tid] = 0; }
    __syncthreads();

    // ---- A fragments (bf16) in registers: [m][s][4] ----
    unsigned au[4][4][4];
#pragma unroll
    for (int m = 0; m < 4; m++)
#pragma unroll
        for (int s = 0; s < 4; s++) {
            int r0 = m * 16 + g, r1 = r0 + 8;
            int kA = 16 * s + 2 * c4, kB = kA + 8;
            au[m][s][0] = pkbf(h2f[r0 * 68 + kA], h2f[r0 * 68 + kA + 1]);
            au[m][s][1] = pkbf(h2f[r1 * 68 + kA], h2f[r1 * 68 + kA + 1]);
            au[m][s][2] = pkbf(h2f[r0 * 68 + kB], h2f[r0 * 68 + kB + 1]);
            au[m][s][3] = pkbf(h2f[r1 * 68 + kB], h2f[r1 * 68 + kB + 1]);
        }

    // ---- stage W tile 0 ----
    const int kp = tid >> 3, fq = tid & 7;   // kpair 0..31, f-quad 0..7
    {
        const float* p = W3 + (size_t)(2 * kp) * FN + fq * 4;
        float4 A0 = *reinterpret_cast<const float4*>(p);
        float4 B0 = *reinterpret_cast<const float4*>(p + FN);
        float4 A1 = *reinterpret_cast<const float4*>(p + 32);
        float4 B1 = *reinterpret_cast<const float4*>(p + FN + 32);
        uint4 w0 = make_uint4(pkbf(A0.x, B0.x), pkbf(A0.y, B0.y),
                              pkbf(A0.z, B0.z), pkbf(A0.w, B0.w));
        uint4 w1 = make_uint4(pkbf(A1.x, B1.x), pkbf(A1.y, B1.y),
                              pkbf(A1.z, B1.z), pkbf(A1.w, B1.w));
        *reinterpret_cast<uint4*>(&wsb[kp * 72 + fq * 4]) = w0;
        *reinterpret_cast<uint4*>(&wsb[kp * 72 + 32 + fq * 4]) = w1;
    }
    __syncthreads();

    float rml[4], rmh[4];
#pragma unroll
    for (int m = 0; m < 4; m++) { rml[m] = -1e30f; rmh[m] = -1e30f; }

    for (int t = 0; t < 128; t++) {
        const int f0 = t * 64;
        unsigned* wcur = wsb + (t & 1) * 2304;
        unsigned* wnxt = wsb + ((t + 1) & 1) * 2304;
        float4 A0, B0, A1, B1;
        if (t < 127) {
            const float* p = W3 + (size_t)(2 * kp) * FN + f0 + 64 + fq * 4;
            A0 = *reinterpret_cast<const float4*>(p);
            B0 = *reinterpret_cast<const float4*>(p + FN);
            A1 = *reinterpret_cast<const float4*>(p + 32);
            B1 = *reinterpret_cast<const float4*>(p + FN + 32);
        }
        float acc[4][4];
#pragma unroll
        for (int m = 0; m < 4; m++) { acc[m][0] = acc[m][1] = acc[m][2] = acc[m][3] = 0.f; }
#pragma unroll
        for (int s = 0; s < 4; s++) {
            unsigned bb0 = wcur[(8 * s + c4) * 72 + wid * 8 + g];
            unsigned bb1 = wcur[(8 * s + c4 + 4) * 72 + wid * 8 + g];
#pragma unroll
            for (int m = 0; m < 4; m++) mma_bf16(acc[m], au[m][s], bb0, bb1);
        }
        const int fc = f0 + wid * 8 + c4 * 2;
        const float2 bias = *reinterpret_cast<const float2*>(b3 + fc);
#pragma unroll
        for (int m = 0; m < 4; m++) {
            float v0 = acc[m][0] + bias.x, v1 = acc[m][1] + bias.y;
            float v2 = acc[m][2] + bias.x, v3 = acc[m][3] + bias.y;
            const int rlo = m * 16 + g, rhi = rlo + 8;
            float m01 = fmaxf(v0, v1), m23 = fmaxf(v2, v3);
            if (m01 > rml[m]) { rml[m] = m01; atomicMax(&rmx[rlo], encf(m01)); }
            if (m23 > rmh[m]) { rmh[m] = m23; atomicMax(&rmx[rhi], encf(m23)); }
            float cl = decf(*(volatile unsigned*)&rmx[rlo]) - MARGIN;
            float ch = decf(*(volatile unsigned*)&rmx[rhi]) - MARGIN;
            if (v0 > cl) { int p = atomicAdd(&scnt[rlo], 1); if (p < CAP) cand[rlo * CAP + p] = fc; }
            if (v1 > cl) { int p = atomicAdd(&scnt[rlo], 1); if (p < CAP) cand[rlo * CAP + p] = fc + 1; }
            if (v2 > ch) { int p = atomicAdd(&scnt[rhi], 1); if (p < CAP) cand[rhi * CAP + p] = fc; }
            if (v3 > ch) { int p = atomicAdd(&scnt[rhi], 1); if (p < CAP) cand[rhi * CAP + p] = fc + 1; }
        }
        if (t < 127) {
            uint4 w0 = make_uint4(pkbf(A0.x, B0.x), pkbf(A0.y, B0.y),
                                  pkbf(A0.z, B0.z), pkbf(A0.w, B0.w));
            uint4 w1 = make_uint4(pkbf(A1.x, B1.x), pkbf(A1.y, B1.y),
                                  pkbf(A1.z, B1.z), pkbf(A1.w, B1.w));
            *reinterpret_cast<uint4*>(&wnxt[kp * 72 + fq * 4]) = w0;
            *reinterpret_cast<uint4*>(&wnxt[kp * 72 + 32 + fq * 4]) = w1;
        }
        __syncthreads();
    }

    // ---- exact refine: warp w owns rows w, w+8, ... ----
    for (int rr = wid; rr < 64; rr += 8) {
        const int row = rb + rr;
        const int c = scnt[rr];
        float bestv = -1e30f; int bestf = 0x7FFFFFFF;
        if (c <= CAP) {
            for (int i = lane; i < c; i += 32) {
                int f = cand[rr * CAP + i];
                float dot = 0.f;
#pragma unroll
                for (int k = 0; k < 64; k++)
                    dot = fmaf(h2f[rr * 68 + k], W3[k * FN + f], dot);
                float logit = __fadd_rn(dot, b3[f]);
                float gg = gumbel_ref(jax_bits((unsigned)row * 8192u + (unsigned)f));
                float v = __fdiv_rn(__fadd_rn(logit, gg), 0.1f);
                if (v > bestv || (v == bestv && f < bestf)) { bestv = v; bestf = f; }
            }
        } else {   // overflow fallback: exact full-row scan with threshold filter
            float th = decf(rmx[rr]) - MARGIN;
            for (int f = lane; f < FN; f += 32) {
                float dot = 0.f;
#pragma unroll
                for (int k = 0; k < 64; k++)
                    dot = fmaf(h2f[rr * 68 + k], W3[k * FN + f], dot);
                float logit = __fadd_rn(dot, b3[f]);
                if (logit > th) {
                    float gg = gumbel_ref(jax_bits((unsigned)row * 8192u + (unsigned)f));
                    float v = __fdiv_rn(__fadd_rn(logit, gg), 0.1f);
                    if (v > bestv || (v == bestv && f < bestf)) { bestv = v; bestf = f; }
                }
            }
        }
#pragma unroll
        for (int off = 16; off > 0; off >>= 1) {
            float ov = __shfl_xor_sync(0xFFFFFFFFu, bestv, off);
            int   of = __shfl_xor_sync(0xFFFFFFFFu, bestf, off);
            if (ov > bestv || (ov == bestv && of < bestf)) { bestv = ov; bestf = of; }
        }
        if (lane == 0) g_ind[row] = bestf;
    }
}

// ---------------- K7: out[row] = codebook[ind[row]] -------------------------
__global__ void k7_gather(const float* __restrict__ codebook, float* __restrict__ out) {
    const int row = blockIdx.x;
    const int ind = g_ind[row];
    const float4* src = reinterpret_cast<const float4*>(codebook + (size_t)ind * DN);
    float4* dst = reinterpret_cast<float4*>(out + (size_t)row * DN);
    dst[threadIdx.x] = src[threadIdx.x];
}

// ---------------- launch ----------------------------------------------------
extern "C" void kernel_launch(void* const* d_in, const int* in_sizes, int n_in,
                              void* d_out, int out_size) {
    const float* x   = (const float*)d_in[0];
    const float* y   = (const float*)d_in[1];
    const float* W1  = (const float*)d_in[2];
    const float* b1  = (const float*)d_in[3];
    const float* g1  = (const float*)d_in[4];
    const float* be1 = (const float*)d_in[5];
    const float* W2  = (const float*)d_in[6];
    const float* b2  = (const float*)d_in[7];
    const float* g2  = (const float*)d_in[8];
    const float* be2 = (const float*)d_in[9];
    const float* W3  = (const float*)d_in[10];
    const float* b3  = (const float*)d_in[11];
    const float* cb  = (const float*)d_in[12];
    float* out = (float*)d_out;

    const int smem3 = (16384 + 4096) * 4 + 512 * 8;                         // 86 KB
    const int smem5 = 64 * 68 * 4 + 2 * 32 * 72 * 4 + 64 * CAP * 4 + 512;   // ~94 KB
    static int attr_set = 0;
    if (!attr_set) {
        cudaFuncSetAttribute(k3_fused, cudaFuncAttributeMaxDynamicSharedMemorySize, smem3);
        cudaFuncSetAttribute(k5_mma, cudaFuncAttributeMaxDynamicSharedMemorySize, smem5);
        attr_set = 1;
    }

    k1_gemm1<<<BN / 8, 256>>>(x, y, W1, b1);
    kstats1<<<64, 256>>>();
    k3_fused<<<BN / 16, 256, smem3>>>(W2, b2, g1, be1);
    k5_mma<<<BN / 64, 256, smem5>>>(W3, b3, g2, be2);
    k7_gather<<<BN, 256>>>(cb, out);
}